// round 17
// baseline (speedup 1.0000x reference)
#include <cuda_runtime.h>
#include <cuda_bf16.h>
#include <cstdint>
#include <cstddef>

#define Bsz 128
#define Tt  256
#define Dd  256
#define Hh  1024
#define Cc  1000
#define NCH 16

__device__ float g_xproj[(size_t)Tt * 32 * 128 * 128];   // [t][j][n128][b]
__device__ char  g_wt[(size_t)128 * 2 * NCH * 4096];     // W tiles [J][term][q][n32][k64]
__device__ char  g_ht[(size_t)2 * 2 * NCH * 16384];      // h tiles [ping][term][q][b128][k64]
__device__ float g_c[(size_t)Hh * Bsz];                  // c [hcol][b]
__device__ float g_hp[(size_t)Hh * Bsz];                 // fp32 h for k_final
__device__ unsigned g_bar;                               // grid barrier counter

__device__ __forceinline__ unsigned long long pack2(float lo, float hi) {
    unsigned long long r; asm("mov.b64 %0, {%1, %2};" : "=l"(r) : "f"(lo), "f"(hi)); return r;
}
__device__ __forceinline__ void fma2(unsigned long long &a, unsigned long long x, unsigned long long y) {
    asm("fma.rn.f32x2 %0, %1, %2, %0;" : "+l"(a) : "l"(x), "l"(y));
}
__device__ __forceinline__ float sigm(float x) { return __fdividef(1.f, 1.f + __expf(-x)); }
__device__ __forceinline__ float tanhx(float x) { return 1.f - __fdividef(2.f, __expf(2.f * x) + 1.f); }
__device__ __forceinline__ void cpa16(uint32_t d, const void* s) {
    asm volatile("cp.async.cg.shared.global [%0], [%1], 16;" :: "r"(d), "l"(s));
}
#define CPA_COMMIT() asm volatile("cp.async.commit_group;")
#define CPA_WAIT0()  asm volatile("cp.async.wait_group 0;")
#define CPA_WAIT1()  asm volatile("cp.async.wait_group 1;")
#define SWZ(off) ((off) ^ (((off) >> 3) & 0x70))

__device__ __forceinline__ uint32_t smem_u32(const void* p) {
    uint32_t a; asm("{ .reg .u64 t; cvta.to.shared.u64 t, %1; cvt.u32.u64 %0, t; }" : "=r"(a) : "l"(p)); return a;
}
__device__ __forceinline__ void ldsm4(uint32_t* r, uint32_t a) {
    asm volatile("ldmatrix.sync.aligned.m8n8.x4.shared.b16 {%0,%1,%2,%3}, [%4];"
        : "=r"(r[0]), "=r"(r[1]), "=r"(r[2]), "=r"(r[3]) : "r"(a));
}
__device__ __forceinline__ void mma16816(float* d, const uint32_t* a, const uint32_t* b) {
    asm volatile("mma.sync.aligned.m16n8k16.row.col.f32.bf16.bf16.f32 "
        "{%0,%1,%2,%3}, {%4,%5,%6,%7}, {%8,%9}, {%0,%1,%2,%3};"
        : "+f"(d[0]), "+f"(d[1]), "+f"(d[2]), "+f"(d[3])
        : "r"(a[0]), "r"(a[1]), "r"(a[2]), "r"(a[3]), "r"(b[0]), "r"(b[1]));
}

__global__ void k_init() {
    int i = blockIdx.x * blockDim.x + threadIdx.x;
    if (i == 0) g_bar = 0u;
    if (i < 131072) { ((uint32_t*)g_ht)[i] = 0u; g_c[i] = 0.f; }  // ping0 tiles + c
}

// W tiles: [J][term][q][n'32][k64] bf16 swizzled; n' = hcl*4+gate, col = J*8+hcl
__global__ __launch_bounds__(128) void k_prep(
    const float* __restrict__ Wg, const float* __restrict__ Wi,
    const float* __restrict__ Wf, const float* __restrict__ Wo)
{
    int J = blockIdx.x >> 4, q = blockIdx.x & 15;
    char* b0 = g_wt + (size_t)((J * 2 + 0) * NCH + q) * 4096;
    char* b1 = g_wt + (size_t)((J * 2 + 1) * NCH + q) * 4096;
    for (int g = threadIdx.x; g < 256; g += 128) {
        int np = g >> 3, k8 = g & 7;
        int gate = np & 3, hcol = J * 8 + (np >> 2);
        const float* W = (gate < 2) ? (gate == 0 ? Wg : Wi) : (gate == 2 ? Wf : Wo);
        alignas(16) __nv_bfloat16 h8[8], l8[8];
#pragma unroll
        for (int i = 0; i < 8; i++) {
            float w = W[(size_t)(q * 64 + k8 * 8 + i) * Hh + hcol];
            __nv_bfloat16 h = __float2bfloat16(w);
            h8[i] = h; l8[i] = __float2bfloat16(w - __bfloat162float(h));
        }
        uint32_t off = SWZ((uint32_t)(np * 128 + k8 * 16));
        *(uint4*)(b0 + off) = *(uint4*)h8;
        *(uint4*)(b1 + off) = *(uint4*)l8;
    }
}

// phase 1: proven FFMA GEMM, xproj [t][j][n128=gate*32+hcl32][b]
__global__ __launch_bounds__(256, 2) void k_input_proj(
    const float* __restrict__ x,
    const float* __restrict__ Wg, const float* __restrict__ Wi,
    const float* __restrict__ Wf, const float* __restrict__ Wo,
    const float* __restrict__ bg, const float* __restrict__ bi,
    const float* __restrict__ bf, const float* __restrict__ bo)
{
    __shared__ float Ws[32][128];
    __shared__ float Xs[32][132];
    int j = blockIdx.x, t = blockIdx.y;
    int tid = threadIdx.x;
    int tn = tid & 15, tb = tid >> 4;
    int n0 = tn * 8, b0 = tb * 8;
    int jb = j * 32;
    int c4w = tid & 31, gatew = c4w >> 3;
    const float* Wsel = (gatew < 2) ? (gatew == 0 ? Wg : Wi) : (gatew == 2 ? Wf : Wo);
    const float* wsrc0 = Wsel + jb + (c4w & 7) * 4;
    unsigned long long acc[32];
#pragma unroll
    for (int q = 0; q < 32; q++) acc[q] = 0ull;
    for (int kc = 0; kc < Dd / 32; kc++) {
        int k0 = kc * 32;
#pragma unroll
        for (int p = 0; p < 4; p++) {
            int row = p * 8 + (tid >> 5);
            *(float4*)&Ws[row][c4w * 4] = *(const float4*)(wsrc0 + (size_t)(k0 + row) * Hh);
        }
#pragma unroll
        for (int p = 0; p < 4; p++) {
            int fi = p * 256 + tid, b = fi >> 3, d4 = fi & 7;
            float4 v = *(const float4*)&x[((size_t)b * Tt + t) * Dd + k0 + d4 * 4];
            Xs[d4 * 4 + 0][b] = v.x; Xs[d4 * 4 + 1][b] = v.y;
            Xs[d4 * 4 + 2][b] = v.z; Xs[d4 * 4 + 3][b] = v.w;
        }
        __syncthreads();
#pragma unroll 4
        for (int kr = 0; kr < 32; kr++) {
            float4 wA = *(const float4*)&Ws[kr][n0];
            float4 wB = *(const float4*)&Ws[kr][n0 + 4];
            float4 xA = *(const float4*)&Xs[kr][b0];
            float4 xB = *(const float4*)&Xs[kr][b0 + 4];
            unsigned long long w0 = pack2(wA.x, wA.y), w1 = pack2(wA.z, wA.w);
            unsigned long long w2 = pack2(wB.x, wB.y), w3 = pack2(wB.z, wB.w);
            float xv[8] = {xA.x, xA.y, xA.z, xA.w, xB.x, xB.y, xB.z, xB.w};
#pragma unroll
            for (int b = 0; b < 8; b++) {
                unsigned long long xb = pack2(xv[b], xv[b]);
                fma2(acc[0 * 8 + b], w0, xb); fma2(acc[1 * 8 + b], w1, xb);
                fma2(acc[2 * 8 + b], w2, xb); fma2(acc[3 * 8 + b], w3, xb);
            }
        }
        __syncthreads();
    }
    float* outp = g_xproj + (((size_t)t * 32 + j) * 128) * 128;
    int gate = n0 >> 5;
    const float* bsel = (gate < 2) ? (gate == 0 ? bg : bi) : (gate == 2 ? bf : bo);
#pragma unroll
    for (int np = 0; np < 4; np++) {
        int n = n0 + 2 * np;
        float bia0 = bsel[jb + (n & 31)], bia1 = bsel[jb + ((n + 1) & 31)];
#pragma unroll
        for (int b = 0; b < 8; b++) {
            float2 v = *(float2*)&acc[np * 8 + b];
            outp[(size_t)n * 128 + b0 + b]       = v.x + bia0;
            outp[(size_t)(n + 1) * 128 + b0 + b] = v.y + bia1;
        }
    }
}

// phase 2: PERSISTENT HMMA stepper, 3-buffer A pipeline + SWP inner loop.
// grid 128 (J), 256 thr. smem: W 128KB | A 3x32KB = 224KB.
#define W_SMEM   131072
#define A_BUF    32768
#define STEP_SMEM (W_SMEM + 3 * A_BUF)

// load all fragments for one ks (A: 4x ldsm4, B: 2x ldsm4 covering both nb)
#define LDFRAG(ks, Ah_, Al_, Bh_, Bl_) do {                                          \
    _Pragma("unroll")                                                                \
    for (int mb = 0; mb < 2; mb++) {                                                 \
        uint32_t offA = SWZ((uint32_t)((wm * 32 + mb * 16 + rowA) * 128 + ((ks) * 16 + kcA) * 2)); \
        ldsm4(Ah_[mb], aAh + offA);                                                  \
        ldsm4(Al_[mb], aAl + offA);                                                  \
    }                                                                                \
    {                                                                                \
        uint32_t offB = SWZ((uint32_t)((wn * 16 + rowB4) * 128 + ((ks) * 16 + kcB) * 2)); \
        ldsm4(Bh_, aBh + offB);                                                      \
        ldsm4(Bl_, aBl + offB);                                                      \
    }                                                                                \
} while (0)

#define MMAS(Ah_, Al_, Bh_, Bl_) do {                                                \
    _Pragma("unroll")                                                                \
    for (int mb = 0; mb < 2; mb++)                                                   \
    _Pragma("unroll")                                                                \
    for (int nb = 0; nb < 2; nb++) {                                                 \
        float* dd = d + (mb * 2 + nb) * 4;                                           \
        mma16816(dd, Ah_[mb], Bh_ + nb * 2);                                         \
        mma16816(dd, Ah_[mb], Bl_ + nb * 2);                                         \
        mma16816(dd, Al_[mb], Bh_ + nb * 2);                                         \
    }                                                                                \
} while (0)

__global__ __launch_bounds__(256, 1) void k_persist()
{
    extern __shared__ __align__(1024) char smx[];
    uint32_t sb = smem_u32(smx);
    int tid = threadIdx.x, wid = tid >> 5, lane = tid & 31;
    int wm = wid & 3, wn = wid >> 2;
    int J = blockIdx.x;

    // load full W slice (128 KB) once
    {
        const char* src = g_wt + (size_t)J * W_SMEM;
#pragma unroll
        for (int p = 0; p < 32; p++) {
            int g = p * 256 + tid;
            cpa16(sb + g * 16, src + g * 16);
        }
        CPA_COMMIT(); CPA_WAIT0();
        __syncthreads();
    }

    int selA = lane >> 3;
    int rowA = (lane & 7) + (selA & 1) * 8;
    int kcA = (selA >> 1) * 8;
    int rowB4 = ((lane >> 4) & 1) * 8 + (lane & 7);   // x4 B: both nb groups
    int kcB = ((lane >> 3) & 1) * 8;
    uint32_t sbA = sb + W_SMEM;
    int bq = tid & 127, hh4 = (tid >> 7) * 4;

    for (int s = 0; s < Tt; s++) {
        int pin = s & 1, pout = pin ^ 1;
        const char* gAh = g_ht + (size_t)(pin * 2 + 0) * NCH * 16384;
        const char* gAl = g_ht + (size_t)(pin * 2 + 1) * NCH * 16384;

        // prefetch epilogue xproj operands into registers
        float xpre[16];
#pragma unroll
        for (int e = 0; e < 4; e++) {
            int hcg = J * 8 + hh4 + e;
            const float* xp = g_xproj + (((size_t)s * 32 + (hcg >> 5)) * 128 + (hcg & 31)) * 128 + bq;
            xpre[e * 4 + 0] = xp[0];
            xpre[e * 4 + 1] = xp[32 * 128];
            xpre[e * 4 + 2] = xp[64 * 128];
            xpre[e * 4 + 3] = xp[96 * 128];
        }

        float d[16];
#pragma unroll
        for (int q = 0; q < 16; q++) d[q] = 0.f;

        // prefetch chunks 0,1 -> bufs 0,1
#pragma unroll
        for (int q0 = 0; q0 < 2; q0++) {
            uint32_t bs = sbA + q0 * A_BUF;
#pragma unroll
            for (int p = 0; p < 4; p++) {
                int g = p * 256 + tid;
                cpa16(bs + g * 16, gAh + (size_t)q0 * 16384 + g * 16);
                cpa16(bs + 16384 + g * 16, gAl + (size_t)q0 * 16384 + g * 16);
            }
            CPA_COMMIT();
        }

        for (int q = 0; q < NCH; q++) {
            if (q < 14) { CPA_WAIT1(); } else { CPA_WAIT0(); }
            __syncthreads();
            if (q + 2 < NCH) {
                int qn = q + 2;
                uint32_t bn = sbA + (qn % 3) * A_BUF;
#pragma unroll
                for (int p = 0; p < 4; p++) {
                    int g = p * 256 + tid;
                    cpa16(bn + g * 16, gAh + (size_t)qn * 16384 + g * 16);
                    cpa16(bn + 16384 + g * 16, gAl + (size_t)qn * 16384 + g * 16);
                }
                CPA_COMMIT();
            }
            uint32_t aAh = sbA + (q % 3) * A_BUF;
            uint32_t aAl = aAh + 16384;
            uint32_t aBh = sb + q * 4096;
            uint32_t aBl = sb + 65536 + q * 4096;

            // software-pipelined ks loop: frags(ks+1) issued before MMAs(ks)
            uint32_t A0h[2][4], A0l[2][4], B0h[4], B0l[4];
            uint32_t A1h[2][4], A1l[2][4], B1h[4], B1l[4];
            LDFRAG(0, A0h, A0l, B0h, B0l);
            LDFRAG(1, A1h, A1l, B1h, B1l);
            MMAS(A0h, A0l, B0h, B0l);
            LDFRAG(2, A0h, A0l, B0h, B0l);
            MMAS(A1h, A1l, B1h, B1l);
            LDFRAG(3, A1h, A1l, B1h, B1l);
            MMAS(A0h, A0l, B0h, B0l);
            MMAS(A1h, A1l, B1h, B1l);
        }
        __syncthreads();   // all reads of last buf done before Ps overlay

        // epilogue (overlay on A buf0)
        float* Ps = (float*)(smx + W_SMEM);
        __nv_bfloat16* Hhi = (__nv_bfloat16*)(smx + W_SMEM + 17408);
        __nv_bfloat16* Hlo = (__nv_bfloat16*)(smx + W_SMEM + 19456);
        int r = lane >> 2, c = (lane & 3) * 2;
#pragma unroll
        for (int mb = 0; mb < 2; mb++)
#pragma unroll
            for (int nb = 0; nb < 2; nb++) {
                float* dd = d + (mb * 2 + nb) * 4;
                int m = wm * 32 + mb * 16 + r, n = wn * 16 + nb * 8 + c;
                Ps[m * 33 + n] = dd[0];       Ps[m * 33 + n + 1] = dd[1];
                Ps[(m + 8) * 33 + n] = dd[2]; Ps[(m + 8) * 33 + n + 1] = dd[3];
            }
        __syncthreads();

#pragma unroll
        for (int e = 0; e < 4; e++) {
            int hcl = hh4 + e;
            int hcg = J * 8 + hcl;
            float pg = Ps[bq * 33 + hcl * 4 + 0] + xpre[e * 4 + 0];
            float pi = Ps[bq * 33 + hcl * 4 + 1] + xpre[e * 4 + 1];
            float pf = Ps[bq * 33 + hcl * 4 + 2] + xpre[e * 4 + 2];
            float po = Ps[bq * 33 + hcl * 4 + 3] + xpre[e * 4 + 3];
            size_t ci = (size_t)hcg * Bsz + bq;
            float gg = tanhx(pg), ii = sigm(pi), ff = sigm(pf), oo = sigm(po);
            float cn = gg * ii + g_c[ci] * ff;
            g_c[ci] = cn;
            float hv = tanhx(cn) * oo;
            g_hp[ci] = hv;
            __nv_bfloat16 hb = __float2bfloat16(hv);
            Hhi[bq * 8 + hcl] = hb;
            Hlo[bq * 8 + hcl] = __float2bfloat16(hv - __bfloat162float(hb));
        }
        __syncthreads();

        {
            int bb = tid & 127, term = tid >> 7;
            int q = J >> 3;
            uint32_t off = SWZ((uint32_t)(bb * 128 + (J & 7) * 16));
            char* dst = g_ht + (size_t)((pout * 2 + term) * NCH + q) * 16384 + off;
            const __nv_bfloat16* src = term ? Hlo : Hhi;
            *(uint4*)dst = *(const uint4*)&src[bb * 8];
        }

        // grid barrier
        __syncthreads();
        __threadfence();
        if (tid == 0) {
            atomicAdd(&g_bar, 1u);
            unsigned target = (unsigned)(s + 1) * 128u;
            unsigned v;
            do {
                asm volatile("ld.acquire.gpu.global.u32 %0, [%1];" : "=r"(v) : "l"(&g_bar));
                if (v < target) __nanosleep(32);
            } while (v < target);
        }
        __syncthreads();
    }
}

// phase 3
__global__ __launch_bounds__(256) void k_final(const float* __restrict__ Wph,
                                               const float* __restrict__ bp,
                                               float* __restrict__ out)
{
    __shared__ float hs[Hh];
    __shared__ float ls[Cc];
    __shared__ float red[256];
    int b = blockIdx.x, tid = threadIdx.x;
    for (int k = tid; k < Hh; k += 256) hs[k] = g_hp[(size_t)k * Bsz + b];
    __syncthreads();
    float acc[4] = {0.f, 0.f, 0.f, 0.f};
    for (int k = 0; k < Hh; k++) {
        float hk = hs[k];
        const float* wr = Wph + (size_t)k * Cc;
#pragma unroll
        for (int q = 0; q < 4; q++) { int n = tid + q * 256; if (n < Cc) acc[q] = fmaf(hk, wr[n], acc[q]); }
    }
    float lmax = -1e30f;
#pragma unroll
    for (int q = 0; q < 4; q++) { int n = tid + q * 256; if (n < Cc) { float v = acc[q] + bp[n]; ls[n] = v; lmax = fmaxf(lmax, v); } }
    red[tid] = lmax; __syncthreads();
    for (int st = 128; st > 0; st >>= 1) { if (tid < st) red[tid] = fmaxf(red[tid], red[tid + st]); __syncthreads(); }
    float mx = red[0]; __syncthreads();
    float lsum = 0.f;
#pragma unroll
    for (int q = 0; q < 4; q++) { int n = tid + q * 256; if (n < Cc) lsum += expf(ls[n] - mx); }
    red[tid] = lsum; __syncthreads();
    for (int st = 128; st > 0; st >>= 1) { if (tid < st) red[tid] += red[tid + st]; __syncthreads(); }
    float lse = logf(red[0]);
#pragma unroll
    for (int q = 0; q < 4; q++) { int n = tid + q * 256; if (n < Cc) out[(size_t)b * Cc + n] = ls[n] - mx - lse; }
}

extern "C" void kernel_launch(void* const* d_in, const int* in_sizes, int n_in,
                              void* d_out, int out_size) {
    const float* x   = (const float*)d_in[0];
    const float* Wgx = (const float*)d_in[1];
    const float* Wix = (const float*)d_in[2];
    const float* Wfx = (const float*)d_in[3];
    const float* Wox = (const float*)d_in[4];
    const float* Wgh = (const float*)d_in[5];
    const float* Wih = (const float*)d_in[6];
    const float* Wfh = (const float*)d_in[7];
    const float* Woh = (const float*)d_in[8];
    const float* Wph = (const float*)d_in[9];
    const float* bg  = (const float*)d_in[10];
    const float* bi  = (const float*)d_in[11];
    const float* bf  = (const float*)d_in[12];
    const float* bo  = (const float*)d_in[13];
    const float* bp  = (const float*)d_in[14];
    float* out = (float*)d_out;

    cudaFuncSetAttribute(k_persist, cudaFuncAttributeMaxDynamicSharedMemorySize, STEP_SMEM);

    k_init<<<512, 256>>>();
    k_prep<<<128 * 16, 128>>>(Wgh, Wih, Wfh, Woh);
    k_input_proj<<<dim3(32, Tt), 256>>>(x, Wgx, Wix, Wfx, Wox, bg, bi, bf, bo);
    k_persist<<<128, 256, STEP_SMEM>>>();
    k_final<<<Bsz, 256>>>(Wph, bp, out);
}